// round 7
// baseline (speedup 1.0000x reference)
#include <cuda_runtime.h>
#include <cstdint>
#include <math.h>

// bayes_55018531062578
//
// out[b] = sigmoid( BEVb[b]-BEVa[b] + (sum_{s<kapa} B[b,k*,s] - A[b,k*,s]) / kapa[b] )
// k*(b,s) = argmax_k ( log_softmax(mean)_k + gumbel(b,s,k) )
// gumbel noise: JAX partitionable threefry counter mode:
//   bits[i] = o0 ^ o1,  (o0,o1) = threefry2x32(key=(0,42), x=(0, i)),
//   u = bitcast((bits>>9)|0x3f800000) - 1
// Fast argmax:  argmax_k (l_k - log(-log(u+eps)+eps)) == argmin_k t_k / w_k,
//   w_k = softmax(mean)_k,  t_k = -log2(u_k+eps)    (monotone transforms)
// Near-tie fallback replays the reference formula in accurate fp32.
//
// Work distribution (R7): 64-thread block per b (2 warps); warp w covers
// chunks {w, w+2, w+4, w+6} (s = 32c+lane). Slot utilization ~90% vs 56%
// for the 8-warp block (dead warps no longer pin 256-thread blocks).

#define EPSF 1e-20f

__device__ __forceinline__ uint32_t rotl32(uint32_t x, int r) {
    return __funnelshift_l(x, x, r);
}

// threefry2x32, key (0,42), input (0, ctr); returns o0 ^ o1
__device__ __forceinline__ uint32_t threefry_xor(uint32_t ctr) {
    const uint32_t ks0 = 0u;
    const uint32_t ks1 = 42u;
    const uint32_t ks2 = 0x1BD11BDAu ^ 42u;

    uint32_t x0 = ks0;
    uint32_t x1 = ctr + ks1;

#define TF4(a,b,c,d) \
    x0 += x1; x1 = rotl32(x1,(a)); x1 ^= x0; \
    x0 += x1; x1 = rotl32(x1,(b)); x1 ^= x0; \
    x0 += x1; x1 = rotl32(x1,(c)); x1 ^= x0; \
    x0 += x1; x1 = rotl32(x1,(d)); x1 ^= x0;

    TF4(13,15,26,6)   x0 += ks1; x1 += ks2 + 1u;
    TF4(17,29,16,24)  x0 += ks2; x1 += ks0 + 2u;
    TF4(13,15,26,6)   x0 += ks0; x1 += ks1 + 3u;
    TF4(17,29,16,24)  x0 += ks1; x1 += ks2 + 4u;
    TF4(13,15,26,6)   x0 += ks2; x1 += ks0 + 5u;
#undef TF4
    return x0 ^ x1;
}

__device__ __forceinline__ float bits_to_uniform(uint32_t bits) {
    return __uint_as_float((bits >> 9) | 0x3f800000u) - 1.0f;
}

__global__ __launch_bounds__(64, 32)
void bayes_kernel(const float* __restrict__ A,
                  const float* __restrict__ Bm,
                  const float* __restrict__ BEVa,
                  const float* __restrict__ BEVb,
                  const int*   __restrict__ kapa,
                  const float* __restrict__ mean,
                  float* __restrict__ out,
                  int S) {
    const int b    = blockIdx.x;
    const int tid  = threadIdx.x;
    const int warp = tid >> 5;       // 0 or 1
    const int lane = tid & 31;

    __shared__ float red[2];

    const int kap = kapa[b];         // issued early; prologue hides latency

    // Prologue: inverse softmax weights (fast path uses argmin t_k * iw_k;
    // the common softmax denominator cancels, so iw_k = 1/exp(m_k - mx)).
    const float m0 = mean[0], m1 = mean[1], m2 = mean[2], m3 = mean[3];
    const float mx = fmaxf(fmaxf(m0, m1), fmaxf(m2, m3));
    const float e0 = __expf(m0 - mx), e1 = __expf(m1 - mx);
    const float e2 = __expf(m2 - mx), e3 = __expf(m3 - mx);
    const float iw[4] = {__fdividef(1.0f, e0), __fdividef(1.0f, e1),
                         __fdividef(1.0f, e2), __fdividef(1.0f, e3)};

    const float* Ab = A  + (size_t)b * 4 * S;
    const float* Bb = Bm + (size_t)b * 4 * S;

    const int nch = (kap + 31) >> 5;          // live 32-sample chunks
    float diff = 0.0f;

    for (int c = warp; c < nch; c += 2) {
        const int s = (c << 5) + lane;
        if (s < kap) {
            const uint32_t base = ((uint32_t)b * (uint32_t)S + (uint32_t)s) * 4u;

            float u[4], q[4];
#pragma unroll
            for (int k = 0; k < 4; k++) {
                const uint32_t bits = threefry_xor(base + (uint32_t)k);
                u[k] = bits_to_uniform(bits);
                const float t = -__log2f(u[k] + EPSF);   // > 0
                q[k] = t * iw[k];
            }

            // argmin with runner-up tracking
            int   kb = 0;
            float best = q[0], second = INFINITY;
            if (q[1] < best) { second = best; best = q[1]; kb = 1; } else second = q[1];
            if (q[2] < best) { second = best; best = q[2]; kb = 2; } else if (q[2] < second) second = q[2];
            if (q[3] < best) { second = best; best = q[3]; kb = 3; } else if (q[3] < second) second = q[3];

            if (second - best < best * 1e-3f) {
                // rare accurate fp32 fallback: exact reference formula
                const float se  = e0 + e1 + e2 + e3;
                const float lse = mx + logf(se);
                const float lg[4] = {m0 - lse, m1 - lse, m2 - lse, m3 - lse};
                float bs = -INFINITY; int kk = 0;
#pragma unroll
                for (int k = 0; k < 4; k++) {
                    const float g  = -logf(-logf(u[k] + EPSF) + EPSF);
                    const float sc = lg[k] + g;
                    if (sc > bs) { bs = sc; kk = k; }
                }
                kb = kk;
            }

            const size_t off = (size_t)kb * S + s;
            diff += Bb[off] - Ab[off];
        }
    }

    // warp reduction, then 2-warp combine
#pragma unroll
    for (int o = 16; o > 0; o >>= 1)
        diff += __shfl_down_sync(0xffffffffu, diff, o);
    if (lane == 0) red[warp] = diff;

    __syncthreads();

    if (tid == 0) {
        const float tot = red[0] + red[1];
        const float x = BEVb[b] - BEVa[b] + tot / (float)kap;
        out[b] = 1.0f / (1.0f + expf(-x));
    }
}

extern "C" void kernel_launch(void* const* d_in, const int* in_sizes, int n_in,
                              void* d_out, int out_size) {
    // metadata order: outcomeA, outcomeB, BEVa, BEVb, kapa, batch_size, features, mean
    const float* A    = (const float*)d_in[0];
    const float* Bm   = (const float*)d_in[1];
    const float* BEVa = (const float*)d_in[2];
    const float* BEVb = (const float*)d_in[3];
    const int*   kapa = (const int*)  d_in[4];

    // mean is the (only) 4-element input; locate it robustly from the tail
    const float* mean = (const float*)d_in[n_in - 1];
    for (int i = n_in - 1; i >= 5; --i) {
        if (in_sizes[i] == 4) { mean = (const float*)d_in[i]; break; }
    }

    float* out = (float*)d_out;

    const int B = in_sizes[2];                 // 16384
    const int S = in_sizes[0] / (4 * B);       // 256

    bayes_kernel<<<B, 64>>>(A, Bm, BEVa, BEVb, kapa, mean, out, S);
}